// round 16
// baseline (speedup 1.0000x reference)
#include <cuda_runtime.h>
#include <cuda_fp16.h>
#include <cstdint>

// GraphSAGE on GB300, fp16 mma.sync + fp16-resident activations.
// R15: W smem staging deleted — B fragments LDG'd per-lane directly from the
// pre-shuffled fragment slab (L1-resident: smem now only 8KB, carveout ~200KB).

#define N_NODES 100000
#define DIM     256
#define KDIM    512
#define NNEIGH  10
#define BM      32
#define KC      64
#define NCHUNK  8
#define THREADS 256

// smem (bytes): just the double-buffered A tile
#define ABUF    4096             // 32 rows x 128B (64 fp16 cols)
#define SMEM_TOTAL (2 * ABUF)    // 8192

__device__ __half g_h0[(size_t)N_NODES * DIM];   // fp16 x
__device__ __half g_h1[(size_t)N_NODES * DIM];
__device__ __half g_h2[(size_t)N_NODES * DIM];
// W fp16 fragments in mma B-frag order: [layer][ktile(32)][ntile(32)][lane(32)][2] u32
__device__ uint32_t g_wfrag[3][32 * 32 * 32 * 2];

__device__ __forceinline__ uint32_t smem_u32(const void* p) {
    uint32_t a;
    asm("{ .reg .u64 t; cvta.to.shared.u64 t, %1; cvt.u32.u64 %0, t; }" : "=r"(a) : "l"(p));
    return a;
}
__device__ __forceinline__ uint32_t sw128(uint32_t off) {
    return off ^ ((off >> 3) & 0x70);
}
__device__ __forceinline__ uint32_t pack_h2(float a, float b) {
    __half2 t = __floats2half2_rn(a, b);
    return *reinterpret_cast<uint32_t*>(&t);
}
__device__ __forceinline__ void ldmat4(uint32_t* r, uint32_t addr) {
    asm volatile("ldmatrix.sync.aligned.m8n8.x4.shared.b16 {%0,%1,%2,%3}, [%4];"
                 : "=r"(r[0]), "=r"(r[1]), "=r"(r[2]), "=r"(r[3]) : "r"(addr));
}
__device__ __forceinline__ void mma16816(float* c, const uint32_t* a, uint32_t b0, uint32_t b1) {
    asm volatile("mma.sync.aligned.m16n8k16.row.col.f32.f16.f16.f32 "
                 "{%0,%1,%2,%3}, {%4,%5,%6,%7}, {%8,%9}, {%0,%1,%2,%3};"
                 : "+f"(c[0]), "+f"(c[1]), "+f"(c[2]), "+f"(c[3])
                 : "r"(a[0]), "r"(a[1]), "r"(a[2]), "r"(a[3]), "r"(b0), "r"(b1));
}
__device__ __forceinline__ void cpasync16(uint32_t smem_dst, const void* gsrc) {
    asm volatile("cp.async.cg.shared.global [%0], [%1], 16;"
                 :: "r"(smem_dst), "l"(gsrc) : "memory");
}
__device__ __forceinline__ void cpasync_commit() {
    asm volatile("cp.async.commit_group;" ::: "memory");
}
__device__ __forceinline__ void cpasync_wait0() {
    asm volatile("cp.async.wait_group 0;" ::: "memory");
}

// -------- x -> fp16 convert --------
__global__ void conv_x(const float* __restrict__ x, __half* __restrict__ o)
{
    const size_t i = ((size_t)blockIdx.x * blockDim.x + threadIdx.x) * 8;
    if (i >= (size_t)N_NODES * DIM) return;
    const float4 a = *(const float4*)(x + i);
    const float4 b = *(const float4*)(x + i + 4);
    uint4 r;
    r.x = pack_h2(a.x, a.y); r.y = pack_h2(a.z, a.w);
    r.z = pack_h2(b.x, b.y); r.w = pack_h2(b.z, b.w);
    *(uint4*)(o + i) = r;
}

// -------- W prep: fp16 convert into mma B-fragment order --------
__global__ void prep_wfrag(const float* __restrict__ W0, const float* __restrict__ W1,
                           const float* __restrict__ W2)
{
    int idx = blockIdx.x * blockDim.x + threadIdx.x;   // [layer][kt][nt][lane]
    if (idx >= 3 * 32 * 32 * 32) return;
    const int lane  = idx & 31;
    const int nt    = (idx >> 5) & 31;
    const int kt    = (idx >> 10) & 31;
    const int layer = idx >> 15;
    const float* W = layer == 0 ? W0 : (layer == 1 ? W1 : W2);
    const int k0 = kt * 16 + (lane & 3) * 2;
    const int n  = nt * 8 + (lane >> 2);

    float v[4] = { W[(k0 + 0) * DIM + n], W[(k0 + 1) * DIM + n],
                   W[(k0 + 8) * DIM + n], W[(k0 + 9) * DIM + n] };
    const size_t base = ((size_t)(kt * 32 + nt) * 32 + lane) * 2;
    g_wfrag[layer][base + 0] = pack_h2(v[0], v[1]);
    g_wfrag[layer][base + 1] = pack_h2(v[2], v[3]);
}

// -------- fused SAGE layer --------
template <bool RELU, bool OUT32>
__global__ __launch_bounds__(THREADS, 2)
void sage_mma(const __half* __restrict__ hin, const int* __restrict__ adj,
              const uint2* __restrict__ wf,     // B-frag slab for this layer
              const float* __restrict__ bias, void* __restrict__ hout_v)
{
    extern __shared__ char smem[];
    const uint32_t sb = smem_u32(smem);
    const int tid  = threadIdx.x;
    const int lane = tid & 31;
    const int wn   = tid >> 5;       // warp n position (cols wn*32..+31)
    const int row0 = blockIdx.x * BM;

    // producer mapping: 8 threads/row, 8 fp16 cols each (16B)
    const int pr = tid >> 3;         // row 0..31
    const int pq = tid & 7;          // 8-col slice of the 64-col chunk
    const int prow = row0 + pr;
    const uint32_t aslot = sw128((uint32_t)(pr * 128 + pq * 16));

    // per-warp B-frag base: fragment (kt, wn*4 + nt) at [(kt*32+wn*4+nt)*32 + lane]
    const uint2* wfw = wf + (size_t)(wn * 4) * 32 + lane;   // + kt*1024 + nt*32

    float c[2][4][4];
    #pragma unroll
    for (int i = 0; i < 2; ++i)
        #pragma unroll
        for (int j = 0; j < 4; ++j)
            #pragma unroll
            for (int k = 0; k < 4; ++k) c[i][j][k] = 0.f;

    // ---- self chunk: single cp.async straight into the swizzled A slot ----
    auto selfcopy = [&](int kc) {
        const int col = (kc & 3) * KC + pq * 8;
        cpasync16(sb + (kc & 1) * ABUF + aslot, hin + (size_t)prow * DIM + col);
    };
    // ---- neighbor gather issue: 16B LDGs into rw ----
    auto issue = [&](int kc, uint4* rw) {
        const int col = (kc & 3) * KC + pq * 8;
        const int* arow = adj + (size_t)prow * NNEIGH;
        int na[NNEIGH];
        #pragma unroll
        for (int j = 0; j < NNEIGH; j += 2) {
            const int2 p = *(const int2*)(arow + j);
            na[j] = p.x; na[j + 1] = p.y;
        }
        #pragma unroll
        for (int j = 0; j < NNEIGH; ++j)
            rw[j] = *(const uint4*)(hin + (size_t)na[j] * DIM + col);
    };
    // ---- neighbor consume: level-1 pairwise hadd2, fp32 finish ----
    auto consume = [&](int kc, const uint4* rw) {
        uint4 p[5];
        #pragma unroll
        for (int j = 0; j < 5; ++j) {
            const __half2* a = (const __half2*)&rw[2 * j];
            const __half2* b = (const __half2*)&rw[2 * j + 1];
            __half2* o = (__half2*)&p[j];
            #pragma unroll
            for (int q = 0; q < 4; ++q) o[q] = __hadd2(a[q], b[q]);
        }
        float2 s[4];
        #pragma unroll
        for (int q = 0; q < 4; ++q) s[q] = make_float2(0.f, 0.f);
        #pragma unroll
        for (int j = 0; j < 5; ++j) {
            const __half2* o = (const __half2*)&p[j];
            #pragma unroll
            for (int q = 0; q < 4; ++q) {
                const float2 f = __half22float2(o[q]);
                s[q].x += f.x; s[q].y += f.y;
            }
        }
        uint4 out;
        out.x = pack_h2(s[0].x * 0.1f, s[0].y * 0.1f);
        out.y = pack_h2(s[1].x * 0.1f, s[1].y * 0.1f);
        out.z = pack_h2(s[2].x * 0.1f, s[2].y * 0.1f);
        out.w = pack_h2(s[3].x * 0.1f, s[3].y * 0.1f);
        *(uint4*)(smem + (kc & 1) * ABUF + aslot) = out;
    };

    // ================= prologue =================
    selfcopy(0);
    cpasync_commit();
    cpasync_wait0();
    __syncthreads();

    // ================= main loop =================
    for (int kc = 0; kc < NCHUNK; ++kc) {
        const bool nxt = kc + 1 < NCHUNK;
        uint4 rw[NNEIGH];
        if (nxt) {
            if (kc + 1 < 4) {
                selfcopy(kc + 1);
                cpasync_commit();
            } else {
                issue(kc + 1, rw);   // LDGs in flight across the MMA block
            }
        }

        // ---- MMA on chunk kc: 4 kt x 8 = 32 MMAs; B frags direct from L1/L2 ----
        const uint32_t Ab = sb + (kc & 1) * ABUF;
        const size_t kbase = (size_t)(kc * 4) * 1024;     // fragment index of kt=0
        uint2 b[4], bn[4];
        #pragma unroll
        for (int nt = 0; nt < 4; ++nt) b[nt] = wfw[kbase + nt * 32];
        #pragma unroll
        for (int kt = 0; kt < 4; ++kt) {
            uint32_t a0[4], a1[4];
            const uint32_t off0 = (uint32_t)((lane & 15) * 128 + kt * 32 + (lane >> 4) * 16);
            ldmat4(a0, Ab + sw128(off0));
            ldmat4(a1, Ab + sw128(off0 + 16 * 128));

            if (kt < 3) {
                #pragma unroll
                for (int nt = 0; nt < 4; ++nt) bn[nt] = wfw[kbase + (kt + 1) * 1024 + nt * 32];
            }
            #pragma unroll
            for (int nt = 0; nt < 4; ++nt) {          // 8 independent accumulators
                mma16816(c[0][nt], a0, b[nt].x, b[nt].y);
                mma16816(c[1][nt], a1, b[nt].x, b[nt].y);
            }
            #pragma unroll
            for (int nt = 0; nt < 4; ++nt) b[nt] = bn[nt];
        }

        if (nxt) {
            if (kc + 1 >= 4) consume(kc + 1, rw);   // data arrived during MMAs
            else             cpasync_wait0();
        }
        __syncthreads();
    }

    // ================= epilogue =================
    float2 bias2[4];
    #pragma unroll
    for (int nt = 0; nt < 4; ++nt)
        bias2[nt] = *(const float2*)&bias[wn * 32 + nt * 8 + (lane & 3) * 2];

    #pragma unroll
    for (int mt = 0; mt < 2; ++mt) {
        const int rbase = row0 + mt * 16 + (lane >> 2);
        #pragma unroll
        for (int h = 0; h < 2; ++h) {
            const int row = rbase + h * 8;
            #pragma unroll
            for (int nt = 0; nt < 4; ++nt) {
                const int n = wn * 32 + nt * 8 + (lane & 3) * 2;
                float ox = c[mt][nt][h * 2 + 0] + bias2[nt].x;
                float oy = c[mt][nt][h * 2 + 1] + bias2[nt].y;
                if (RELU) { ox = fmaxf(ox, 0.f); oy = fmaxf(oy, 0.f); }
                if (OUT32) {
                    *(float2*)((float*)hout_v + (size_t)row * DIM + n) = make_float2(ox, oy);
                } else {
                    *(uint32_t*)((__half*)hout_v + (size_t)row * DIM + n) = pack_h2(ox, oy);
                }
            }
        }
    }
}

extern "C" void kernel_launch(void* const* d_in, const int* in_sizes, int n_in,
                              void* d_out, int out_size)
{
    const float* x   = (const float*)d_in[0];
    const int*   adj = (const int*)  d_in[1];
    const float* W0  = (const float*)d_in[2];
    const float* b0  = (const float*)d_in[3];
    const float* W1  = (const float*)d_in[4];
    const float* b1  = (const float*)d_in[5];
    const float* W2  = (const float*)d_in[6];
    const float* b2  = (const float*)d_in[7];
    float* out = (float*)d_out;

    void *p0, *p1, *p2, *pwf;
    cudaGetSymbolAddress(&p0, g_h0);
    cudaGetSymbolAddress(&p1, g_h1);
    cudaGetSymbolAddress(&p2, g_h2);
    cudaGetSymbolAddress(&pwf, g_wfrag);
    __half* xh = (__half*)p0;
    __half* h1 = (__half*)p1;
    __half* h2 = (__half*)p2;
    const uint2* wf = (const uint2*)pwf;
    const size_t WSZ = 32 * 32 * 32;   // uint2 per layer

    prep_wfrag<<<(3 * 32 * 32 * 32 + 255) / 256, 256>>>(W0, W1, W2);
    conv_x<<<(N_NODES * DIM / 8 + 255) / 256, 256>>>(x, xh);

    const int grid = N_NODES / BM;   // 3125
    sage_mma<true,  false><<<grid, THREADS, SMEM_TOTAL>>>(xh, adj, wf,           b0, h1);
    sage_mma<true,  false><<<grid, THREADS, SMEM_TOTAL>>>(h1, adj, wf + WSZ,     b1, h2);
    sage_mma<false, true ><<<grid, THREADS, SMEM_TOTAL>>>(h2, adj, wf + 2 * WSZ, b2, out);
}

// round 17
// speedup vs baseline: 1.4050x; 1.4050x over previous
#include <cuda_runtime.h>
#include <cuda_fp16.h>
#include <cstdint>

// GraphSAGE on GB300, fp16 mma.sync + fp16-resident activations.
// R17: phase-decoupled layer. Build the full 32x512 A panel in smem (1 barrier),
// then a barrier-free MMA sweep with per-lane B-fragment LDGs (L1-resident).
// Cross-phase overlap comes from co-resident CTAs at staggered phases.

#define N_NODES 100000
#define DIM     256
#define KDIM    512
#define NNEIGH  10
#define BM      32
#define KC      64
#define NCHUNK  8
#define THREADS 256

// smem: full A panel, 8 chunk regions x 4KB
#define ABUF    4096
#define SMEM_TOTAL (NCHUNK * ABUF)    // 32768

__device__ __half g_h0[(size_t)N_NODES * DIM];   // fp16 x
__device__ __half g_h1[(size_t)N_NODES * DIM];
__device__ __half g_h2[(size_t)N_NODES * DIM];
// W fp16 fragments in mma B-frag order: [layer][ktile(32)][ntile(32)][lane(32)][2] u32
__device__ uint32_t g_wfrag[3][32 * 32 * 32 * 2];

__device__ __forceinline__ uint32_t smem_u32(const void* p) {
    uint32_t a;
    asm("{ .reg .u64 t; cvta.to.shared.u64 t, %1; cvt.u32.u64 %0, t; }" : "=r"(a) : "l"(p));
    return a;
}
__device__ __forceinline__ uint32_t sw128(uint32_t off) {
    return off ^ ((off >> 3) & 0x70);
}
__device__ __forceinline__ uint32_t pack_h2(float a, float b) {
    __half2 t = __floats2half2_rn(a, b);
    return *reinterpret_cast<uint32_t*>(&t);
}
__device__ __forceinline__ void ldmat4(uint32_t* r, uint32_t addr) {
    asm volatile("ldmatrix.sync.aligned.m8n8.x4.shared.b16 {%0,%1,%2,%3}, [%4];"
                 : "=r"(r[0]), "=r"(r[1]), "=r"(r[2]), "=r"(r[3]) : "r"(addr));
}
__device__ __forceinline__ void mma16816(float* c, const uint32_t* a, uint32_t b0, uint32_t b1) {
    asm volatile("mma.sync.aligned.m16n8k16.row.col.f32.f16.f16.f32 "
                 "{%0,%1,%2,%3}, {%4,%5,%6,%7}, {%8,%9}, {%0,%1,%2,%3};"
                 : "+f"(c[0]), "+f"(c[1]), "+f"(c[2]), "+f"(c[3])
                 : "r"(a[0]), "r"(a[1]), "r"(a[2]), "r"(a[3]), "r"(b0), "r"(b1));
}
__device__ __forceinline__ void cpasync16(uint32_t smem_dst, const void* gsrc) {
    asm volatile("cp.async.cg.shared.global [%0], [%1], 16;"
                 :: "r"(smem_dst), "l"(gsrc) : "memory");
}
__device__ __forceinline__ void cpasync_commit() {
    asm volatile("cp.async.commit_group;" ::: "memory");
}
__device__ __forceinline__ void cpasync_wait0() {
    asm volatile("cp.async.wait_group 0;" ::: "memory");
}

// -------- x -> fp16 convert --------
__global__ void conv_x(const float* __restrict__ x, __half* __restrict__ o)
{
    const size_t i = ((size_t)blockIdx.x * blockDim.x + threadIdx.x) * 8;
    if (i >= (size_t)N_NODES * DIM) return;
    const float4 a = *(const float4*)(x + i);
    const float4 b = *(const float4*)(x + i + 4);
    uint4 r;
    r.x = pack_h2(a.x, a.y); r.y = pack_h2(a.z, a.w);
    r.z = pack_h2(b.x, b.y); r.w = pack_h2(b.z, b.w);
    *(uint4*)(o + i) = r;
}

// -------- W prep: fp16 convert into mma B-fragment order --------
__global__ void prep_wfrag(const float* __restrict__ W0, const float* __restrict__ W1,
                           const float* __restrict__ W2)
{
    int idx = blockIdx.x * blockDim.x + threadIdx.x;   // [layer][kt][nt][lane]
    if (idx >= 3 * 32 * 32 * 32) return;
    const int lane  = idx & 31;
    const int nt    = (idx >> 5) & 31;
    const int kt    = (idx >> 10) & 31;
    const int layer = idx >> 15;
    const float* W = layer == 0 ? W0 : (layer == 1 ? W1 : W2);
    const int k0 = kt * 16 + (lane & 3) * 2;
    const int n  = nt * 8 + (lane >> 2);

    float v[4] = { W[(k0 + 0) * DIM + n], W[(k0 + 1) * DIM + n],
                   W[(k0 + 8) * DIM + n], W[(k0 + 9) * DIM + n] };
    const size_t base = ((size_t)(kt * 32 + nt) * 32 + lane) * 2;
    g_wfrag[layer][base + 0] = pack_h2(v[0], v[1]);
    g_wfrag[layer][base + 1] = pack_h2(v[2], v[3]);
}

// -------- fused SAGE layer --------
template <bool RELU, bool OUT32>
__global__ __launch_bounds__(THREADS, 2)
void sage_mma(const __half* __restrict__ hin, const int* __restrict__ adj,
              const uint2* __restrict__ wf,     // B-frag slab for this layer
              const float* __restrict__ bias, void* __restrict__ hout_v)
{
    extern __shared__ char smem[];
    const uint32_t sb = smem_u32(smem);
    const int tid  = threadIdx.x;
    const int lane = tid & 31;
    const int wn   = tid >> 5;       // warp n position (cols wn*32..+31)
    const int row0 = blockIdx.x * BM;

    // producer mapping: 8 threads/row, 8 fp16 cols each (16B)
    const int pr = tid >> 3;         // row 0..31
    const int pq = tid & 7;          // 8-col slice of each 64-col chunk
    const int prow = row0 + pr;
    const uint32_t aslot = sw128((uint32_t)(pr * 128 + pq * 16));

    // per-warp B-frag base: fragment (kt, wn*4+nt) at [(kt*32+wn*4+nt)*32 + lane]
    const uint2* wfw = wf + (size_t)(wn * 4) * 32 + lane;

    // ================= BUILD PHASE =================
    // self chunks 0..3: straight cp.async into swizzled slots
    #pragma unroll
    for (int kc = 0; kc < 4; ++kc) {
        const int col = kc * KC + pq * 8;
        cpasync16(sb + kc * ABUF + aslot, hin + (size_t)prow * DIM + col);
    }
    cpasync_commit();

    // neighbor chunks 4..7: LDG -> pairwise hadd2 -> fp32 finish -> STS
    {
        const int* arow = adj + (size_t)prow * NNEIGH;
        int na[NNEIGH];
        #pragma unroll
        for (int j = 0; j < NNEIGH; j += 2) {
            const int2 p = *(const int2*)(arow + j);
            na[j] = p.x; na[j + 1] = p.y;
        }
        #pragma unroll
        for (int kc = 4; kc < 8; ++kc) {
            const int col = (kc - 4) * KC + pq * 8;
            uint4 rw[NNEIGH];
            #pragma unroll
            for (int j = 0; j < NNEIGH; ++j)
                rw[j] = *(const uint4*)(hin + (size_t)na[j] * DIM + col);

            uint4 p[5];
            #pragma unroll
            for (int j = 0; j < 5; ++j) {
                const __half2* a = (const __half2*)&rw[2 * j];
                const __half2* b = (const __half2*)&rw[2 * j + 1];
                __half2* o = (__half2*)&p[j];
                #pragma unroll
                for (int q = 0; q < 4; ++q) o[q] = __hadd2(a[q], b[q]);
            }
            float2 s[4];
            #pragma unroll
            for (int q = 0; q < 4; ++q) s[q] = make_float2(0.f, 0.f);
            #pragma unroll
            for (int j = 0; j < 5; ++j) {
                const __half2* o = (const __half2*)&p[j];
                #pragma unroll
                for (int q = 0; q < 4; ++q) {
                    const float2 f = __half22float2(o[q]);
                    s[q].x += f.x; s[q].y += f.y;
                }
            }
            uint4 out;
            out.x = pack_h2(s[0].x * 0.1f, s[0].y * 0.1f);
            out.y = pack_h2(s[1].x * 0.1f, s[1].y * 0.1f);
            out.z = pack_h2(s[2].x * 0.1f, s[2].y * 0.1f);
            out.w = pack_h2(s[3].x * 0.1f, s[3].y * 0.1f);
            *(uint4*)(smem + kc * ABUF + aslot) = out;
        }
    }
    cpasync_wait0();
    __syncthreads();     // the ONLY barrier in the layer body

    // ================= MMA SWEEP (barrier-free) =================
    float c[2][4][4];
    #pragma unroll
    for (int i = 0; i < 2; ++i)
        #pragma unroll
        for (int j = 0; j < 4; ++j)
            #pragma unroll
            for (int k = 0; k < 4; ++k) c[i][j][k] = 0.f;

    #pragma unroll
    for (int kc = 0; kc < NCHUNK; ++kc) {
        const uint32_t Ab = sb + kc * ABUF;
        const size_t kbase = (size_t)(kc * 4) * 1024;
        uint2 b[4], bn[4];
        #pragma unroll
        for (int nt = 0; nt < 4; ++nt) b[nt] = wfw[kbase + nt * 32];
        #pragma unroll
        for (int kt = 0; kt < 4; ++kt) {
            uint32_t a0[4], a1[4];
            const uint32_t off0 = (uint32_t)((lane & 15) * 128 + kt * 32 + (lane >> 4) * 16);
            ldmat4(a0, Ab + sw128(off0));
            ldmat4(a1, Ab + sw128(off0 + 16 * 128));

            if (kt < 3) {
                #pragma unroll
                for (int nt = 0; nt < 4; ++nt) bn[nt] = wfw[kbase + (kt + 1) * 1024 + nt * 32];
            } else if (kc < NCHUNK - 1) {
                #pragma unroll
                for (int nt = 0; nt < 4; ++nt) bn[nt] = wfw[kbase + 4 * 1024 + nt * 32];
            }
            #pragma unroll
            for (int nt = 0; nt < 4; ++nt) {          // 8 independent accumulators
                mma16816(c[0][nt], a0, b[nt].x, b[nt].y);
                mma16816(c[1][nt], a1, b[nt].x, b[nt].y);
            }
            #pragma unroll
            for (int nt = 0; nt < 4; ++nt) b[nt] = bn[nt];
        }
    }

    // ================= epilogue =================
    float2 bias2[4];
    #pragma unroll
    for (int nt = 0; nt < 4; ++nt)
        bias2[nt] = *(const float2*)&bias[wn * 32 + nt * 8 + (lane & 3) * 2];

    #pragma unroll
    for (int mt = 0; mt < 2; ++mt) {
        const int rbase = row0 + mt * 16 + (lane >> 2);
        #pragma unroll
        for (int h = 0; h < 2; ++h) {
            const int row = rbase + h * 8;
            #pragma unroll
            for (int nt = 0; nt < 4; ++nt) {
                const int n = wn * 32 + nt * 8 + (lane & 3) * 2;
                float ox = c[mt][nt][h * 2 + 0] + bias2[nt].x;
                float oy = c[mt][nt][h * 2 + 1] + bias2[nt].y;
                if (RELU) { ox = fmaxf(ox, 0.f); oy = fmaxf(oy, 0.f); }
                if (OUT32) {
                    *(float2*)((float*)hout_v + (size_t)row * DIM + n) = make_float2(ox, oy);
                } else {
                    *(uint32_t*)((__half*)hout_v + (size_t)row * DIM + n) = pack_h2(ox, oy);
                }
            }
        }
    }
}

extern "C" void kernel_launch(void* const* d_in, const int* in_sizes, int n_in,
                              void* d_out, int out_size)
{
    const float* x   = (const float*)d_in[0];
    const int*   adj = (const int*)  d_in[1];
    const float* W0  = (const float*)d_in[2];
    const float* b0  = (const float*)d_in[3];
    const float* W1  = (const float*)d_in[4];
    const float* b1  = (const float*)d_in[5];
    const float* W2  = (const float*)d_in[6];
    const float* b2  = (const float*)d_in[7];
    float* out = (float*)d_out;

    void *p0, *p1, *p2, *pwf;
    cudaGetSymbolAddress(&p0, g_h0);
    cudaGetSymbolAddress(&p1, g_h1);
    cudaGetSymbolAddress(&p2, g_h2);
    cudaGetSymbolAddress(&pwf, g_wfrag);
    __half* xh = (__half*)p0;
    __half* h1 = (__half*)p1;
    __half* h2 = (__half*)p2;
    const uint2* wf = (const uint2*)pwf;
    const size_t WSZ = 32 * 32 * 32;   // uint2 per layer

    prep_wfrag<<<(3 * 32 * 32 * 32 + 255) / 256, 256>>>(W0, W1, W2);
    conv_x<<<(N_NODES * DIM / 8 + 255) / 256, 256>>>(x, xh);

    const int grid = N_NODES / BM;   // 3125
    sage_mma<true,  false><<<grid, THREADS, SMEM_TOTAL>>>(xh, adj, wf,           b0, h1);
    sage_mma<true,  false><<<grid, THREADS, SMEM_TOTAL>>>(h1, adj, wf + WSZ,     b1, h2);
    sage_mma<false, true ><<<grid, THREADS, SMEM_TOTAL>>>(h2, adj, wf + 2 * WSZ, b2, out);
}